// round 13
// baseline (speedup 1.0000x reference)
#include <cuda_runtime.h>

#define NB 2048
#define NN 64
#define DM 512
#define NH 4
#define DK 128
#define TB 16

typedef unsigned long long ull;

__device__ float g_Wqf[DM * NH];
__device__ float g_Wkf[DM * NH];
__device__ float g_ctx[NB * NH * DM];      // [b][h][i]
__device__ float g_WvT[DM * DM];           // [i4][col] float4-tiled
__device__ float g_fcwT[DM * DM];
__device__ float g_fc1T[(DM + DK) * DK];
__device__ float g_fc2T[DK * DK];

// ---- f32x2 packed-FMA helpers (sm_100+) ------------------------------------
__device__ __forceinline__ ull pk(float a, float b) {
    ull r; asm("mov.b64 %0,{%1,%2};" : "=l"(r) : "f"(a), "f"(b)); return r;
}
__device__ __forceinline__ void fma2(ull &d, ull a, ull b) {
    asm("fma.rn.f32x2 %0,%1,%2,%0;" : "+l"(d) : "l"(a), "l"(b));
}
__device__ __forceinline__ float2 up(ull a) {
    float2 f; asm("mov.b64 {%0,%1},%2;" : "=f"(f.x), "=f"(f.y) : "l"(a)); return f;
}

// ---------------------------------------------------------------------------
// K0a: fold Wq/Wk with w_map halves. grid 512, block 128 (warp = head).
// ---------------------------------------------------------------------------
__global__ void __launch_bounds__(128) fold_kernel(
    const float* __restrict__ Wq, const float* __restrict__ Wk,
    const float* __restrict__ w_map)
{
    __shared__ float4 s_m[64];
    int i = blockIdx.x;
    int t = threadIdx.x;
    int lane = t & 31, h = t >> 5;
    if (t < 64) s_m[t] = ((const float4*)w_map)[t];
    __syncthreads();
    float4 vq = ((const float4*)(Wq + i * DM + h * DK))[lane];
    float4 vk = ((const float4*)(Wk + i * DM + h * DK))[lane];
    float4 mq = s_m[lane], mk = s_m[32 + lane];
    float sq = vq.x * mq.x + vq.y * mq.y + vq.z * mq.z + vq.w * mq.w;
    float sk = vk.x * mk.x + vk.y * mk.y + vk.z * mk.z + vk.w * mk.w;
#pragma unroll
    for (int o = 16; o > 0; o >>= 1) {
        sq += __shfl_xor_sync(0xffffffffu, sq, o);
        sk += __shfl_xor_sync(0xffffffffu, sk, o);
    }
    if (lane == 0) {
        g_Wqf[i * NH + h] = sq;
        g_Wkf[i * NH + h] = sk;
    }
}

// ---------------------------------------------------------------------------
// K0b: tile-transpose weights: W'[i4][col] = float4(W[4i4+0..3][col])
// ---------------------------------------------------------------------------
__global__ void __launch_bounds__(256) wtile_kernel(
    const float* __restrict__ Wv,  const float* __restrict__ fcw,
    const float* __restrict__ fc1w, const float* __restrict__ fc2w)
{
    int idx = blockIdx.x * 256 + threadIdx.x;
    if (idx < 65536) {
        int i4 = idx >> 9, col = idx & 511;
        const float* w = Wv + (size_t)i4 * 4 * DM + col;
        ((float4*)g_WvT)[idx] = make_float4(w[0], w[DM], w[2 * DM], w[3 * DM]);
    } else if (idx < 131072) {
        int j = idx - 65536;
        int i4 = j >> 9, col = j & 511;
        const float* w = fcw + (size_t)i4 * 4 * DM + col;
        ((float4*)g_fcwT)[j] = make_float4(w[0], w[DM], w[2 * DM], w[3 * DM]);
    } else if (idx < 151552) {
        int j = idx - 131072;               // 160 i4 x 128 col
        int i4 = j >> 7, col = j & 127;
        const float* w = fc1w + (size_t)i4 * 4 * DK + col;
        ((float4*)g_fc1T)[j] = make_float4(w[0], w[DK], w[2 * DK], w[3 * DK]);
    } else if (idx < 155648) {
        int j = idx - 151552;               // 32 i4 x 128 col
        int i4 = j >> 7, col = j & 127;
        const float* w = fc2w + (size_t)i4 * 4 * DK + col;
        ((float4*)g_fc2T)[j] = make_float4(w[0], w[DK], w[2 * DK], w[3 * DK]);
    }
}

// ---------------------------------------------------------------------------
// K1: scores + masked softmax + ctx (pass-2 re-read, temporally L2-hot).
// grid 2048, block 256, natural occupancy (no pad).
// ---------------------------------------------------------------------------
__global__ void __launch_bounds__(256) score_kernel(
    const float* __restrict__ src,  const float* __restrict__ srct,
    const float* __restrict__ srcp,
    const float* __restrict__ seq,  const float* __restrict__ seqe,
    const float* __restrict__ seqt, const float* __restrict__ seqp,
    const int*   __restrict__ mask, float* __restrict__ out_attn)
{
    __shared__ float4 s_wkf[DM];
    __shared__ float s_score[NH][NN];
    __shared__ float s_qp[4][NH];
    __shared__ float s_qs[NH];
    __shared__ float4 s_att4[NN];       // [k] -> attn for 4 heads
    __shared__ float4 s_part[DK * NH];  // pass-2 partials [i4][h]

    int b = blockIdx.x;
    int t = threadIdx.x;

    const float4* gwkf = (const float4*)g_Wkf;
    s_wkf[t]       = gwkf[t];
    s_wkf[t + 256] = gwkf[t + 256];

    if (t < DK) {
        float a  = src[b * DK + t];
        float tt = srct[b * DK + t];
        float pp = srcp[b * DK + t];
        const float4* gwqf = (const float4*)g_Wqf;
        float4 w0 = gwqf[t];
        float4 w1 = gwqf[2 * DK + t];
        float4 w2 = gwqf[3 * DK + t];
        float q0 = a * w0.x + tt * w1.x + pp * w2.x;
        float q1 = a * w0.y + tt * w1.y + pp * w2.y;
        float q2 = a * w0.z + tt * w1.z + pp * w2.z;
        float q3 = a * w0.w + tt * w1.w + pp * w2.w;
#pragma unroll
        for (int o = 16; o > 0; o >>= 1) {
            q0 += __shfl_xor_sync(0xffffffffu, q0, o);
            q1 += __shfl_xor_sync(0xffffffffu, q1, o);
            q2 += __shfl_xor_sync(0xffffffffu, q2, o);
            q3 += __shfl_xor_sync(0xffffffffu, q3, o);
        }
        if ((t & 31) == 0) {
            int w = t >> 5;
            s_qp[w][0] = q0; s_qp[w][1] = q1; s_qp[w][2] = q2; s_qp[w][3] = q3;
        }
    }
    __syncthreads();

    // pass 1: k_score, warp w -> rows w*8..w*8+7 (coalesced 128B row chunks)
    {
        int w = t >> 5, lane = t & 31;
#pragma unroll
        for (int r = 0; r < 8; r++) {
            int k = w * 8 + r;
            float a0 = 0.f, a1 = 0.f, a2 = 0.f, a3 = 0.f;
#pragma unroll
            for (int seg = 0; seg < 4; seg++) {
                const float* kin = (seg == 0) ? seq : (seg == 1) ? seqe
                                  : (seg == 2) ? seqt : seqp;
                const float* row = kin + (size_t)(b * NN + k) * DK;
#pragma unroll
                for (int j = 0; j < 4; j++) {
                    float v = row[j * 32 + lane];
                    float4 wv = s_wkf[seg * DK + j * 32 + lane];
                    a0 += v * wv.x; a1 += v * wv.y;
                    a2 += v * wv.z; a3 += v * wv.w;
                }
            }
#pragma unroll
            for (int o = 16; o > 0; o >>= 1) {
                a0 += __shfl_xor_sync(0xffffffffu, a0, o);
                a1 += __shfl_xor_sync(0xffffffffu, a1, o);
                a2 += __shfl_xor_sync(0xffffffffu, a2, o);
                a3 += __shfl_xor_sync(0xffffffffu, a3, o);
            }
            if (lane == 0) {
                s_score[0][k] = a0; s_score[1][k] = a1;
                s_score[2][k] = a2; s_score[3][k] = a3;
            }
        }
    }
    __syncthreads();

    if (t < NH) s_qs[t] = s_qp[0][t] + s_qp[1][t] + s_qp[2][t] + s_qp[3][t];
    __syncthreads();

    // softmax: warp h handles head h
    if (t < 128) {
        int h = t >> 5, l = t & 31;
        float qs = s_qs[h];
        int m0 = mask[b * NN + l];
        int m1 = mask[b * NN + l + 32];
        float v0 = m0 ? -1e10f : qs + s_score[h][l];
        float v1 = m1 ? -1e10f : qs + s_score[h][l + 32];
        float mx = fmaxf(v0, v1);
#pragma unroll
        for (int o = 16; o > 0; o >>= 1) mx = fmaxf(mx, __shfl_xor_sync(0xffffffffu, mx, o));
        float e0 = expf(v0 - mx), e1 = expf(v1 - mx);
        float s = e0 + e1;
#pragma unroll
        for (int o = 16; o > 0; o >>= 1) s += __shfl_xor_sync(0xffffffffu, s, o);
        float inv = 1.f / s;
        e0 *= inv; e1 *= inv;
        out_attn[b * (NH * NN) + h * NN + l]      = e0;
        out_attn[b * (NH * NN) + h * NN + l + 32] = e1;
        ((float*)s_att4)[l * 4 + h]        = e0;
        ((float*)s_att4)[(l + 32) * 4 + h] = e1;
    }
    __syncthreads();

    // pass 2: ctx[h][i] = sum_k attn[h][k] * k_in[k][i]; re-read (L2-hot)
    {
        int i4 = t & 127, ks = t >> 7;
        int seg = i4 >> 5;
        int col4 = i4 & 31;
        const float* kin = (seg == 0) ? seq : (seg == 1) ? seqe
                          : (seg == 2) ? seqt : seqp;
        const float4* base = (const float4*)(kin + (size_t)b * NN * DK) + col4;
        float4 c0 = make_float4(0.f, 0.f, 0.f, 0.f);
        float4 c1 = c0, c2 = c0, c3 = c0;
        int k0 = ks * 32;
#pragma unroll 4
        for (int k = k0; k < k0 + 32; k++) {
            float4 v = base[k * 32];
            float4 a = s_att4[k];
            c0.x += a.x * v.x; c0.y += a.x * v.y; c0.z += a.x * v.z; c0.w += a.x * v.w;
            c1.x += a.y * v.x; c1.y += a.y * v.y; c1.z += a.y * v.z; c1.w += a.y * v.w;
            c2.x += a.z * v.x; c2.y += a.z * v.y; c2.z += a.z * v.z; c2.w += a.z * v.w;
            c3.x += a.w * v.x; c3.y += a.w * v.y; c3.z += a.w * v.z; c3.w += a.w * v.w;
        }
        if (ks) {
            s_part[i4 * 4 + 0] = c0; s_part[i4 * 4 + 1] = c1;
            s_part[i4 * 4 + 2] = c2; s_part[i4 * 4 + 3] = c3;
        }
        __syncthreads();
        if (!ks) {
            float4 p0 = s_part[i4 * 4 + 0], p1 = s_part[i4 * 4 + 1];
            float4 p2 = s_part[i4 * 4 + 2], p3 = s_part[i4 * 4 + 3];
            c0.x += p0.x; c0.y += p0.y; c0.z += p0.z; c0.w += p0.w;
            c1.x += p1.x; c1.y += p1.y; c1.z += p1.z; c1.w += p1.w;
            c2.x += p2.x; c2.y += p2.y; c2.z += p2.z; c2.w += p2.w;
            c3.x += p3.x; c3.y += p3.y; c3.z += p3.z; c3.w += p3.w;
            float4* gc = (float4*)(g_ctx + (size_t)b * NH * DM);
            gc[0 * 128 + i4] = c0;
            gc[1 * 128 + i4] = c1;
            gc[2 * 128 + i4] = c2;
            gc[3 * 128 + i4] = c3;
        }
    }
}

// ---------------------------------------------------------------------------
// K2: GEMM chain on staged ctx. TB=16, 128 CTAs, block 512, 172KB smem.
// Phases 2/3: 2 cols x 8 rows per thread -> half the broadcast-LDS wavefronts.
// ---------------------------------------------------------------------------
#define SM_CTX  0        // [16][2048] f (32768) ; aliases: ln [16][512], h1
#define SM_OUT  32768    // [16][512]  (8192)    ; alias: part [3][16][128]
#define SM_SRC  40960    // [16][128]  (2048)
#define SM_TOTF 43008
#define SM_H1   8192     // alias in ctx region (after ln's 8192 floats)

__global__ void __launch_bounds__(512, 1) tail_kernel(
    const float* __restrict__ src,  const float* __restrict__ srct,
    const float* __restrict__ srcp,
    const float* __restrict__ fcb,  const float* __restrict__ lng,
    const float* __restrict__ lnb,  const float* __restrict__ fc1b,
    const float* __restrict__ fc2b, float* __restrict__ zout)
{
    extern __shared__ float sm[];
    ulonglong2* ctxU = (ulonglong2*)sm;
    float*      out_s = sm + SM_OUT;
    ulonglong2* outU  = (ulonglong2*)out_s;
    float*      src_s = sm + SM_SRC;
    ulonglong2* srcU  = (ulonglong2*)src_s;
    float*      ln_s  = sm;
    ulonglong2* lnU   = (ulonglong2*)sm;
    float*      h1_s  = sm + SM_H1;
    ulonglong2* h1U   = (ulonglong2*)h1_s;
    float*      part  = out_s;            // alias, phases 5/6 only

    int t = threadIdx.x;
    int b0 = blockIdx.x * TB;

    // stage ctx + src
    {
        const float4* gc = (const float4*)g_ctx + (size_t)b0 * DM;
        float4* c4s = (float4*)sm;
        for (int idx = t; idx < TB * NH * DM / 4; idx += 512) c4s[idx] = gc[idx];
        const float4* gs = (const float4*)(src + (size_t)b0 * DK);
        float4* s4 = (float4*)src_s;
        for (int idx = t; idx < TB * DK / 4; idx += 512) s4[idx] = gs[idx];
    }
    __syncthreads();

    int c = t & 255, rg2 = t >> 8;        // col owner, row group (0/1)

    // Phase 2: out[r][h*128+d] = sum_i ctx[r][h][i]*Wv[i][h*128+d]
    // cols paired within a head: (h, d2) and (h, d2+64); 8 rows per thread.
    {
        int h2 = c >> 6, d2 = c & 63;
        ull acc0[8], acc1[8];
#pragma unroll
        for (int r = 0; r < 8; r++) { acc0[r] = 0; acc1[r] = 0; }
        const float4* wpa = (const float4*)g_WvT + (h2 * DK + d2);
        const float4* wpb = wpa + 64;
#pragma unroll 2
        for (int i4 = 0; i4 < 128; i4++) {
            float4 wa = wpa[i4 * 512], wb = wpb[i4 * 512];
            ull wa1 = pk(wa.x, wa.y), wa2 = pk(wa.z, wa.w);
            ull wb1 = pk(wb.x, wb.y), wb2 = pk(wb.z, wb.w);
#pragma unroll
            for (int r = 0; r < 8; r++) {
                ulonglong2 cx = ctxU[(rg2 * 8 + r) * 512 + h2 * 128 + i4];  // broadcast
                fma2(acc0[r], cx.x, wa1); fma2(acc0[r], cx.y, wa2);
                fma2(acc1[r], cx.x, wb1); fma2(acc1[r], cx.y, wb2);
            }
        }
#pragma unroll
        for (int r = 0; r < 8; r++) {
            int row = rg2 * 8 + r;
            float2 f0 = up(acc0[r]), f1 = up(acc1[r]);
            out_s[row * DM + h2 * DK + d2]      = f0.x + f0.y;
            out_s[row * DM + h2 * DK + d2 + 64] = f1.x + f1.y;
        }
    }
    __syncthreads();

    // Phase 3: fc + leaky -> ln_s ; cols c and c+256, 8 rows per thread
    {
        ull acc0[8], acc1[8];
#pragma unroll
        for (int r = 0; r < 8; r++) { acc0[r] = 0; acc1[r] = 0; }
        const float4* wpa = (const float4*)g_fcwT + c;
        const float4* wpb = wpa + 256;
#pragma unroll 2
        for (int i4 = 0; i4 < 128; i4++) {
            float4 wa = wpa[i4 * 512], wb = wpb[i4 * 512];
            ull wa1 = pk(wa.x, wa.y), wa2 = pk(wa.z, wa.w);
            ull wb1 = pk(wb.x, wb.y), wb2 = pk(wb.z, wb.w);
#pragma unroll
            for (int r = 0; r < 8; r++) {
                ulonglong2 x = outU[(rg2 * 8 + r) * 128 + i4];              // broadcast
                fma2(acc0[r], x.x, wa1); fma2(acc0[r], x.y, wa2);
                fma2(acc1[r], x.x, wb1); fma2(acc1[r], x.y, wb2);
            }
        }
        float bb0 = fcb[c], bb1 = fcb[c + 256];
#pragma unroll
        for (int r = 0; r < 8; r++) {
            int row = rg2 * 8 + r;
            float2 f0 = up(acc0[r]), f1 = up(acc1[r]);
            float v0 = f0.x + f0.y + bb0; v0 = (v0 > 0.f) ? v0 : 0.2f * v0;
            float v1 = f1.x + f1.y + bb1; v1 = (v1 > 0.f) ? v1 : 0.2f * v1;
            ln_s[row * DM + c]       = v0;
            ln_s[row * DM + c + 256] = v1;
        }
    }
    __syncthreads();

    // Phase 4: residual (+q_in) + layernorm, warp w -> row w (16 warps)
    {
        int w = t >> 5, l = t & 31;
        int gb = b0 + w;
        float y[16];
        float sum = 0.f, sumsq = 0.f;
#pragma unroll
        for (int e = 0; e < 16; e++) {
            int j = l + e * 32;
            float q;
            if (j < 128)       q = src_s[w * DK + j];
            else if (j < 256)  q = 0.f;
            else if (j < 384)  q = srct[(size_t)gb * DK + (j - 256)];
            else               q = srcp[(size_t)gb * DK + (j - 384)];
            float v = ln_s[w * DM + j] + q;
            y[e] = v; sum += v; sumsq += v * v;
        }
#pragma unroll
        for (int o = 16; o > 0; o >>= 1) {
            sum   += __shfl_xor_sync(0xffffffffu, sum, o);
            sumsq += __shfl_xor_sync(0xffffffffu, sumsq, o);
        }
        float mu  = sum * (1.f / 512.f);
        float var = sumsq * (1.f / 512.f) - mu * mu;
        float inv = rsqrtf(var + 1e-5f);
#pragma unroll
        for (int e = 0; e < 16; e++) {
            int j = l + e * 32;
            ln_s[w * DM + j] = (y[e] - mu) * inv * lng[j] + lnb[j];
        }
    }
    __syncthreads();

    int h = t >> 7, d = t & 127;
    int q = h;   // K-quarter 0..3

    // Phase 5: fc1 (K=640, split 4 ways) + relu -> h1_s
    {
        ull acc[TB];
#pragma unroll
        for (int r = 0; r < TB; r++) acc[r] = 0;
        const float4* wp = (const float4*)g_fc1T + d;
        int i40 = q * 32;
#pragma unroll 2
        for (int i4 = i40; i4 < i40 + 32; i4++) {
            float4 w4 = wp[i4 * 128];
            ull wA = pk(w4.x, w4.y), wB = pk(w4.z, w4.w);
#pragma unroll
            for (int r = 0; r < TB; r++) {
                ulonglong2 x = lnU[r * 128 + i4];              // broadcast
                fma2(acc[r], x.x, wA); fma2(acc[r], x.y, wB);
            }
        }
        int j40 = q * 8;
#pragma unroll 2
        for (int j4 = j40; j4 < j40 + 8; j4++) {
            float4 w4 = wp[(128 + j4) * 128];
            ull wA = pk(w4.x, w4.y), wB = pk(w4.z, w4.w);
#pragma unroll
            for (int r = 0; r < TB; r++) {
                ulonglong2 x = srcU[r * 32 + j4];              // broadcast
                fma2(acc[r], x.x, wA); fma2(acc[r], x.y, wB);
            }
        }
        if (q > 0) {
#pragma unroll
            for (int r = 0; r < TB; r++) {
                float2 f = up(acc[r]);
                part[(q - 1) * 2048 + r * 128 + d] = f.x + f.y;
            }
        }
        __syncthreads();
        if (q == 0) {
            float bb = fc1b[d];
#pragma unroll
            for (int r = 0; r < TB; r++) {
                float2 f = up(acc[r]);
                float v = f.x + f.y + part[0 * 2048 + r * 128 + d]
                        + part[1 * 2048 + r * 128 + d]
                        + part[2 * 2048 + r * 128 + d] + bb;
                h1_s[r * DK + d] = fmaxf(v, 0.f);
            }
        }
        __syncthreads();
    }

    // Phase 6: fc2 (K=128, split 4 ways) -> z
    {
        ull acc[TB];
#pragma unroll
        for (int r = 0; r < TB; r++) acc[r] = 0;
        const float4* wp = (const float4*)g_fc2T + d;
        int j40 = q * 8;
#pragma unroll 2
        for (int j4 = j40; j4 < j40 + 8; j4++) {
            float4 w4 = wp[j4 * 128];
            ull wA = pk(w4.x, w4.y), wB = pk(w4.z, w4.w);
#pragma unroll
            for (int r = 0; r < TB; r++) {
                ulonglong2 x = h1U[r * 32 + j4];               // broadcast
                fma2(acc[r], x.x, wA); fma2(acc[r], x.y, wB);
            }
        }
        if (q > 0) {
#pragma unroll
            for (int r = 0; r < TB; r++) {
                float2 f = up(acc[r]);
                part[(q - 1) * 2048 + r * 128 + d] = f.x + f.y;
            }
        }
        __syncthreads();
        if (q == 0) {
            float bb = fc2b[d];
#pragma unroll
            for (int r = 0; r < TB; r++) {
                float2 f = up(acc[r]);
                zout[(size_t)(b0 + r) * DK + d] = f.x + f.y
                    + part[0 * 2048 + r * 128 + d]
                    + part[1 * 2048 + r * 128 + d]
                    + part[2 * 2048 + r * 128 + d] + bb;
            }
        }
    }
}

// ---------------------------------------------------------------------------
extern "C" void kernel_launch(void* const* d_in, const int* in_sizes, int n_in,
                              void* d_out, int out_size) {
    (void)in_sizes; (void)n_in; (void)out_size;
    const float* src   = (const float*)d_in[0];
    const float* src_t = (const float*)d_in[1];
    const float* src_p = (const float*)d_in[2];
    const float* seq   = (const float*)d_in[3];
    const float* seq_t = (const float*)d_in[4];
    const float* seq_e = (const float*)d_in[5];
    const float* seq_p = (const float*)d_in[6];
    const int*   mask  = (const int*)d_in[7];
    const float* Wq    = (const float*)d_in[8];
    const float* Wk    = (const float*)d_in[9];
    const float* Wv    = (const float*)d_in[10];
    const float* w_map = (const float*)d_in[11];
    const float* fc_w  = (const float*)d_in[12];
    const float* fc_b  = (const float*)d_in[13];
    const float* ln_g  = (const float*)d_in[14];
    const float* ln_b  = (const float*)d_in[15];
    const float* fc1_w = (const float*)d_in[16];
    const float* fc1_b = (const float*)d_in[17];
    const float* fc2_w = (const float*)d_in[18];
    const float* fc2_b = (const float*)d_in[19];

    float* out      = (float*)d_out;
    float* z_out    = out;                 // [2048,1,128]
    float* attn_out = out + NB * DK;       // [2048,4,1,64]

    fold_kernel<<<DM, 128>>>(Wq, Wk, w_map);
    wtile_kernel<<<608, 256>>>(Wv, fc_w, fc1_w, fc2_w);

    score_kernel<<<NB, 256>>>(src, src_t, src_p,
                              seq, seq_e, seq_t, seq_p,
                              mask, attn_out);

    const int smem2 = SM_TOTF * (int)sizeof(float);
    cudaFuncSetAttribute(tail_kernel, cudaFuncAttributeMaxDynamicSharedMemorySize, smem2);
    tail_kernel<<<NB / TB, 512, smem2>>>(src, src_t, src_p,
                                         fc_b, ln_g, ln_b, fc1_b, fc2_b, z_out);
}

// round 14
// speedup vs baseline: 1.0825x; 1.0825x over previous
#include <cuda_runtime.h>

#define NB 2048
#define NN 64
#define DM 512
#define NH 4
#define DK 128
#define TB 16

typedef unsigned long long ull;

__device__ float g_Wqf[DM * NH];
__device__ float g_Wkf[DM * NH];
__device__ float g_attnT[NB * NN * NH];    // [b][k][h]
__device__ float g_WvT[DM * DM];           // [i4][col] float4-tiled
__device__ float g_fcwT[DM * DM];
__device__ float g_fc1T[(DM + DK) * DK];
__device__ float g_fc2T[DK * DK];

// ---- f32x2 packed-FMA helpers (sm_100+) ------------------------------------
__device__ __forceinline__ ull pk(float a, float b) {
    ull r; asm("mov.b64 %0,{%1,%2};" : "=l"(r) : "f"(a), "f"(b)); return r;
}
__device__ __forceinline__ void fma2(ull &d, ull a, ull b) {
    asm("fma.rn.f32x2 %0,%1,%2,%0;" : "+l"(d) : "l"(a), "l"(b));
}
__device__ __forceinline__ float2 up(ull a) {
    float2 f; asm("mov.b64 {%0,%1},%2;" : "=f"(f.x), "=f"(f.y) : "l"(a)); return f;
}

// ---------------------------------------------------------------------------
// K0a: fold Wq/Wk with w_map halves. grid 512, block 128 (warp = head).
// ---------------------------------------------------------------------------
__global__ void __launch_bounds__(128) fold_kernel(
    const float* __restrict__ Wq, const float* __restrict__ Wk,
    const float* __restrict__ w_map)
{
    __shared__ float4 s_m[64];
    int i = blockIdx.x;
    int t = threadIdx.x;
    int lane = t & 31, h = t >> 5;
    if (t < 64) s_m[t] = ((const float4*)w_map)[t];
    __syncthreads();
    float4 vq = ((const float4*)(Wq + i * DM + h * DK))[lane];
    float4 vk = ((const float4*)(Wk + i * DM + h * DK))[lane];
    float4 mq = s_m[lane], mk = s_m[32 + lane];
    float sq = vq.x * mq.x + vq.y * mq.y + vq.z * mq.z + vq.w * mq.w;
    float sk = vk.x * mk.x + vk.y * mk.y + vk.z * mk.z + vk.w * mk.w;
#pragma unroll
    for (int o = 16; o > 0; o >>= 1) {
        sq += __shfl_xor_sync(0xffffffffu, sq, o);
        sk += __shfl_xor_sync(0xffffffffu, sk, o);
    }
    if (lane == 0) {
        g_Wqf[i * NH + h] = sq;
        g_Wkf[i * NH + h] = sk;
    }
}

// ---------------------------------------------------------------------------
// K0b: tile-transpose weights: W'[i4][col] = float4(W[4i4+0..3][col])
// ---------------------------------------------------------------------------
__global__ void __launch_bounds__(256) wtile_kernel(
    const float* __restrict__ Wv,  const float* __restrict__ fcw,
    const float* __restrict__ fc1w, const float* __restrict__ fc2w)
{
    int idx = blockIdx.x * 256 + threadIdx.x;
    if (idx < 65536) {
        int i4 = idx >> 9, col = idx & 511;
        const float* w = Wv + (size_t)i4 * 4 * DM + col;
        ((float4*)g_WvT)[idx] = make_float4(w[0], w[DM], w[2 * DM], w[3 * DM]);
    } else if (idx < 131072) {
        int j = idx - 65536;
        int i4 = j >> 9, col = j & 511;
        const float* w = fcw + (size_t)i4 * 4 * DM + col;
        ((float4*)g_fcwT)[j] = make_float4(w[0], w[DM], w[2 * DM], w[3 * DM]);
    } else if (idx < 151552) {
        int j = idx - 131072;               // 160 i4 x 128 col
        int i4 = j >> 7, col = j & 127;
        const float* w = fc1w + (size_t)i4 * 4 * DK + col;
        ((float4*)g_fc1T)[j] = make_float4(w[0], w[DK], w[2 * DK], w[3 * DK]);
    } else if (idx < 155648) {
        int j = idx - 151552;               // 32 i4 x 128 col
        int i4 = j >> 7, col = j & 127;
        const float* w = fc2w + (size_t)i4 * 4 * DK + col;
        ((float4*)g_fc2T)[j] = make_float4(w[0], w[DK], w[2 * DK], w[3 * DK]);
    }
}

// ---------------------------------------------------------------------------
// K1: scores + masked softmax only (R9 version, proven ~70us). grid 2048.
// ---------------------------------------------------------------------------
__global__ void __launch_bounds__(256) score_kernel(
    const float* __restrict__ src,  const float* __restrict__ srct,
    const float* __restrict__ srcp,
    const float* __restrict__ seq,  const float* __restrict__ seqe,
    const float* __restrict__ seqt, const float* __restrict__ seqp,
    const int*   __restrict__ mask, float* __restrict__ out_attn)
{
    __shared__ float4 s_wkf[DM];
    __shared__ float s_score[NH][NN];
    __shared__ float s_qp[4][NH];
    __shared__ float s_qs[NH];

    int b = blockIdx.x;
    int t = threadIdx.x;

    const float4* gwkf = (const float4*)g_Wkf;
    s_wkf[t]       = gwkf[t];
    s_wkf[t + 256] = gwkf[t + 256];

    if (t < DK) {
        float a  = src[b * DK + t];
        float tt = srct[b * DK + t];
        float pp = srcp[b * DK + t];
        const float4* gwqf = (const float4*)g_Wqf;
        float4 w0 = gwqf[t];
        float4 w1 = gwqf[2 * DK + t];
        float4 w2 = gwqf[3 * DK + t];
        float q0 = a * w0.x + tt * w1.x + pp * w2.x;
        float q1 = a * w0.y + tt * w1.y + pp * w2.y;
        float q2 = a * w0.z + tt * w1.z + pp * w2.z;
        float q3 = a * w0.w + tt * w1.w + pp * w2.w;
#pragma unroll
        for (int o = 16; o > 0; o >>= 1) {
            q0 += __shfl_xor_sync(0xffffffffu, q0, o);
            q1 += __shfl_xor_sync(0xffffffffu, q1, o);
            q2 += __shfl_xor_sync(0xffffffffu, q2, o);
            q3 += __shfl_xor_sync(0xffffffffu, q3, o);
        }
        if ((t & 31) == 0) {
            int w = t >> 5;
            s_qp[w][0] = q0; s_qp[w][1] = q1; s_qp[w][2] = q2; s_qp[w][3] = q3;
        }
    }
    __syncthreads();

    {
        int w = t >> 5, lane = t & 31;
#pragma unroll
        for (int r = 0; r < 8; r++) {
            int k = w * 8 + r;
            float a0 = 0.f, a1 = 0.f, a2 = 0.f, a3 = 0.f;
#pragma unroll
            for (int seg = 0; seg < 4; seg++) {
                const float* kin = (seg == 0) ? seq : (seg == 1) ? seqe
                                  : (seg == 2) ? seqt : seqp;
                const float* row = kin + (size_t)(b * NN + k) * DK;
#pragma unroll
                for (int j = 0; j < 4; j++) {
                    float v = row[j * 32 + lane];
                    float4 wv = s_wkf[seg * DK + j * 32 + lane];
                    a0 += v * wv.x; a1 += v * wv.y;
                    a2 += v * wv.z; a3 += v * wv.w;
                }
            }
#pragma unroll
            for (int o = 16; o > 0; o >>= 1) {
                a0 += __shfl_xor_sync(0xffffffffu, a0, o);
                a1 += __shfl_xor_sync(0xffffffffu, a1, o);
                a2 += __shfl_xor_sync(0xffffffffu, a2, o);
                a3 += __shfl_xor_sync(0xffffffffu, a3, o);
            }
            if (lane == 0) {
                s_score[0][k] = a0; s_score[1][k] = a1;
                s_score[2][k] = a2; s_score[3][k] = a3;
            }
        }
    }
    __syncthreads();

    if (t < NH) s_qs[t] = s_qp[0][t] + s_qp[1][t] + s_qp[2][t] + s_qp[3][t];
    __syncthreads();

    if (t < 128) {
        int h = t >> 5, l = t & 31;
        float qs = s_qs[h];
        int m0 = mask[b * NN + l];
        int m1 = mask[b * NN + l + 32];
        float v0 = m0 ? -1e10f : qs + s_score[h][l];
        float v1 = m1 ? -1e10f : qs + s_score[h][l + 32];
        float mx = fmaxf(v0, v1);
#pragma unroll
        for (int o = 16; o > 0; o >>= 1) mx = fmaxf(mx, __shfl_xor_sync(0xffffffffu, mx, o));
        float e0 = expf(v0 - mx), e1 = expf(v1 - mx);
        float s = e0 + e1;
#pragma unroll
        for (int o = 16; o > 0; o >>= 1) s += __shfl_xor_sync(0xffffffffu, s, o);
        float inv = 1.f / s;
        e0 *= inv; e1 *= inv;
        out_attn[b * (NH * NN) + h * NN + l]      = e0;
        out_attn[b * (NH * NN) + h * NN + l + 32] = e1;
        g_attnT[(size_t)(b * NN + l) * NH + h]      = e0;
        g_attnT[(size_t)(b * NN + l + 32) * NH + h] = e1;
    }
}

// ---------------------------------------------------------------------------
// K2: R9 structure (stream phase-1 + GEMM chain, TB=16, block 512) with
// R10's f4-transposed weights + explicit 1-ahead weight prefetch.
// ---------------------------------------------------------------------------
#define SM_CTX  0        // [16][2048] f (32768) ; aliases: ln [16][512], h1
#define SM_ATT  32768    // [16][64] float4 (4096 f)
#define SM_OUT  36864    // [16][512]  (8192 f)  ; alias: part [3][16][128]
#define SM_SRC  45056    // [16][128]  (2048 f)
#define SM_TOTF 47104
#define SM_H1   8192     // alias in ctx region (after ln's 8192 floats)

__global__ void __launch_bounds__(512, 1) tail_kernel(
    const float* __restrict__ src,  const float* __restrict__ srct,
    const float* __restrict__ srcp,
    const float* __restrict__ seq,  const float* __restrict__ seqe,
    const float* __restrict__ seqt, const float* __restrict__ seqp,
    const float* __restrict__ fcb,  const float* __restrict__ lng,
    const float* __restrict__ lnb,  const float* __restrict__ fc1b,
    const float* __restrict__ fc2b, float* __restrict__ zout)
{
    extern __shared__ float sm[];
    ulonglong2* ctxU = (ulonglong2*)sm;
    float4*     att4 = (float4*)(sm + SM_ATT);
    float*      out_s = sm + SM_OUT;
    ulonglong2* outU  = (ulonglong2*)out_s;
    float*      src_s = sm + SM_SRC;
    ulonglong2* srcU  = (ulonglong2*)src_s;
    float*      ln_s  = sm;
    ulonglong2* lnU   = (ulonglong2*)sm;
    float*      h1_s  = sm + SM_H1;
    ulonglong2* h1U   = (ulonglong2*)h1_s;
    float*      part  = out_s;            // alias, phases 5/6 only

    int t = threadIdx.x;
    int b0 = blockIdx.x * TB;

    // stage attn (transposed) + src
    {
        const float4* ga = (const float4*)(g_attnT + (size_t)b0 * NN * NH);
        for (int idx = t; idx < TB * NN; idx += 512) att4[idx] = ga[idx];
        const float4* gs = (const float4*)(src + (size_t)b0 * DK);
        float4* s4 = (float4*)src_s;
        for (int idx = t; idx < TB * DK / 4; idx += 512) s4[idx] = gs[idx];
    }
    __syncthreads();

    int rg = t >> 7;          // 0..3
    int c4 = t & 127;

    // Phase 1: ctx[r][h][i] = sum_k attn[r][k][h] * k_in[r][k][i]
    // 2 independent row streams per thread + 1-deep prefetch. (R9, proven)
    {
        int seg = c4 >> 5, col = c4 & 31;
        const float* kin = (seg == 0) ? seq : (seg == 1) ? seqe
                          : (seg == 2) ? seqt : seqp;
#pragma unroll 1
        for (int rp = 0; rp < 2; rp++) {
            int r0 = rg * 4 + rp * 2;
            int r1 = r0 + 1;
            const ulonglong2* p0 = (const ulonglong2*)(kin + (size_t)(b0 + r0) * NN * DK) + col;
            const ulonglong2* p1 = (const ulonglong2*)(kin + (size_t)(b0 + r1) * NN * DK) + col;
            ull Ax[NH], Ay[NH], Bx[NH], By[NH];
#pragma unroll
            for (int h = 0; h < NH; h++) { Ax[h] = 0; Ay[h] = 0; Bx[h] = 0; By[h] = 0; }
            ulonglong2 va = p0[0], vb = p1[0];
#pragma unroll 4
            for (int k = 0; k < NN; k++) {
                ulonglong2 van, vbn;
                if (k < NN - 1) { van = p0[(k + 1) * 32]; vbn = p1[(k + 1) * 32]; }
                float4 a0 = att4[r0 * NN + k];
                float4 a1 = att4[r1 * NN + k];
                ull e00 = pk(a0.x, a0.x), e01 = pk(a0.y, a0.y);
                ull e02 = pk(a0.z, a0.z), e03 = pk(a0.w, a0.w);
                ull e10 = pk(a1.x, a1.x), e11 = pk(a1.y, a1.y);
                ull e12 = pk(a1.z, a1.z), e13 = pk(a1.w, a1.w);
                fma2(Ax[0], e00, va.x); fma2(Ay[0], e00, va.y);
                fma2(Ax[1], e01, va.x); fma2(Ay[1], e01, va.y);
                fma2(Ax[2], e02, va.x); fma2(Ay[2], e02, va.y);
                fma2(Ax[3], e03, va.x); fma2(Ay[3], e03, va.y);
                fma2(Bx[0], e10, vb.x); fma2(By[0], e10, vb.y);
                fma2(Bx[1], e11, vb.x); fma2(By[1], e11, vb.y);
                fma2(Bx[2], e12, vb.x); fma2(By[2], e12, vb.y);
                fma2(Bx[3], e13, vb.x); fma2(By[3], e13, vb.y);
                va = van; vb = vbn;
            }
#pragma unroll
            for (int h = 0; h < NH; h++) {
                ulonglong2 u; u.x = Ax[h]; u.y = Ay[h];
                ctxU[r0 * 512 + h * 128 + c4] = u;
                ulonglong2 w; w.x = Bx[h]; w.y = By[h];
                ctxU[r1 * 512 + h * 128 + c4] = w;
            }
        }
    }
    __syncthreads();

    int h = rg, d = c4;

    // Phase 2: out[r][h*128+d] = sum_i ctx[r][h][i]*Wv[i][h*128+d]
    {
        ull acc[TB];
#pragma unroll
        for (int r = 0; r < TB; r++) acc[r] = 0;
        const float4* wp = (const float4*)g_WvT + (h * DK + d);
        float4 wn = wp[0];
#pragma unroll 2
        for (int i4 = 0; i4 < 128; i4++) {
            float4 w4 = wn;
            if (i4 < 127) wn = wp[(i4 + 1) * 512];     // 1-ahead prefetch
            ull wA = pk(w4.x, w4.y), wB = pk(w4.z, w4.w);
#pragma unroll
            for (int r = 0; r < TB; r++) {
                ulonglong2 c = ctxU[r * 512 + h * 128 + i4];   // broadcast
                fma2(acc[r], c.x, wA);
                fma2(acc[r], c.y, wB);
            }
        }
#pragma unroll
        for (int r = 0; r < TB; r++) {
            float2 f = up(acc[r]);
            out_s[r * DM + h * DK + d] = f.x + f.y;
        }
    }
    __syncthreads();

    // Phase 3: fc + leaky -> ln_s ; thread owns col t (512 cols)
    {
        ull acc[TB];
#pragma unroll
        for (int r = 0; r < TB; r++) acc[r] = 0;
        const float4* wp = (const float4*)g_fcwT + t;
        float4 wn = wp[0];
#pragma unroll 2
        for (int i4 = 0; i4 < 128; i4++) {
            float4 w4 = wn;
            if (i4 < 127) wn = wp[(i4 + 1) * 512];
            ull wA = pk(w4.x, w4.y), wB = pk(w4.z, w4.w);
#pragma unroll
            for (int r = 0; r < TB; r++) {
                ulonglong2 x = outU[r * 128 + i4];             // broadcast
                fma2(acc[r], x.x, wA);
                fma2(acc[r], x.y, wB);
            }
        }
        float bb = fcb[t];
#pragma unroll
        for (int r = 0; r < TB; r++) {
            float2 f = up(acc[r]);
            float v = f.x + f.y + bb;
            v = (v > 0.f) ? v : 0.2f * v;
            ln_s[r * DM + t] = v;
        }
    }
    __syncthreads();

    // Phase 4: residual (+q_in) + layernorm, warp w -> row w (16 warps)
    {
        int w = t >> 5, l = t & 31;
        int gb = b0 + w;
        float y[16];
        float sum = 0.f, sumsq = 0.f;
#pragma unroll
        for (int e = 0; e < 16; e++) {
            int j = l + e * 32;
            float q;
            if (j < 128)       q = src_s[w * DK + j];
            else if (j < 256)  q = 0.f;
            else if (j < 384)  q = srct[(size_t)gb * DK + (j - 256)];
            else               q = srcp[(size_t)gb * DK + (j - 384)];
            float v = ln_s[w * DM + j] + q;
            y[e] = v; sum += v; sumsq += v * v;
        }
#pragma unroll
        for (int o = 16; o > 0; o >>= 1) {
            sum   += __shfl_xor_sync(0xffffffffu, sum, o);
            sumsq += __shfl_xor_sync(0xffffffffu, sumsq, o);
        }
        float mu  = sum * (1.f / 512.f);
        float var = sumsq * (1.f / 512.f) - mu * mu;
        float inv = rsqrtf(var + 1e-5f);
#pragma unroll
        for (int e = 0; e < 16; e++) {
            int j = l + e * 32;
            ln_s[w * DM + j] = (y[e] - mu) * inv * lng[j] + lnb[j];
        }
    }
    __syncthreads();

    int q = rg;   // K-quarter 0..3

    // Phase 5: fc1 (K=640, split 4 ways) + relu -> h1_s
    {
        ull acc[TB];
#pragma unroll
        for (int r = 0; r < TB; r++) acc[r] = 0;
        const float4* wp = (const float4*)g_fc1T + d;
        int i40 = q * 32;
        float4 wn = wp[i40 * 128];
#pragma unroll 2
        for (int i4 = i40; i4 < i40 + 32; i4++) {
            float4 w4 = wn;
            if (i4 < i40 + 31) wn = wp[(i4 + 1) * 128];
            ull wA = pk(w4.x, w4.y), wB = pk(w4.z, w4.w);
#pragma unroll
            for (int r = 0; r < TB; r++) {
                ulonglong2 x = lnU[r * 128 + i4];              // broadcast
                fma2(acc[r], x.x, wA); fma2(acc[r], x.y, wB);
            }
        }
        int j40 = q * 8;
        float4 wm = wp[(128 + j40) * 128];
#pragma unroll 2
        for (int j4 = j40; j4 < j40 + 8; j4++) {
            float4 w4 = wm;
            if (j4 < j40 + 7) wm = wp[(128 + j4 + 1) * 128];
            ull wA = pk(w4.x, w4.y), wB = pk(w4.z, w4.w);
#pragma unroll
            for (int r = 0; r < TB; r++) {
                ulonglong2 x = srcU[r * 32 + j4];              // broadcast
                fma2(acc[r], x.x, wA); fma2(acc[r], x.y, wB);
            }
        }
        if (q > 0) {
#pragma unroll
            for (int r = 0; r < TB; r++) {
                float2 f = up(acc[r]);
                part[(q - 1) * 2048 + r * 128 + d] = f.x + f.y;
            }
        }
        __syncthreads();
        if (q == 0) {
            float bb = fc1b[d];
#pragma unroll
            for (int r = 0; r < TB; r++) {
                float2 f = up(acc[r]);
                float v = f.x + f.y + part[0 * 2048 + r * 128 + d]
                        + part[1 * 2048 + r * 128 + d]
                        + part[2 * 2048 + r * 128 + d] + bb;
                h1_s[r * DK + d] = fmaxf(v, 0.f);
            }
        }
        __syncthreads();
    }

    // Phase 6: fc2 (K=128, split 4 ways) -> z
    {
        ull acc[TB];
#pragma unroll
        for (int r = 0; r < TB; r++) acc[r] = 0;
        const float4* wp = (const float4*)g_fc2T + d;
        int j40 = q * 8;
        float4 wn = wp[j40 * 128];
#pragma unroll 2
        for (int j4 = j40; j4 < j40 + 8; j4++) {
            float4 w4 = wn;
            if (j4 < j40 + 7) wn = wp[(j4 + 1) * 128];
            ull wA = pk(w4.x, w4.y), wB = pk(w4.z, w4.w);
#pragma unroll
            for (int r = 0; r < TB; r++) {
                ulonglong2 x = h1U[r * 32 + j4];               // broadcast
                fma2(acc[r], x.x, wA); fma2(acc[r], x.y, wB);
            }
        }
        if (q > 0) {
#pragma unroll
            for (int r = 0; r < TB; r++) {
                float2 f = up(acc[r]);
                part[(q - 1) * 2048 + r * 128 + d] = f.x + f.y;
            }
        }
        __syncthreads();
        if (q == 0) {
            float bb = fc2b[d];
#pragma unroll
            for (int r = 0; r < TB; r++) {
                float2 f = up(acc[r]);
                zout[(size_t)(b0 + r) * DK + d] = f.x + f.y
                    + part[0 * 2048 + r * 128 + d]
                    + part[1 * 2048 + r * 128 + d]
                    + part[2 * 2048 + r * 128 + d] + bb;
            }
        }
    }
}

// ---------------------------------------------------------------------------
extern "C" void kernel_launch(void* const* d_in, const int* in_sizes, int n_in,
                              void* d_out, int out_size) {
    (void)in_sizes; (void)n_in; (void)out_size;
    const float* src   = (const float*)d_in[0];
    const float* src_t = (const float*)d_in[1];
    const float* src_p = (const float*)d_in[2];
    const float* seq   = (const float*)d_in[3];
    const float* seq_t = (const float*)d_in[4];
    const float* seq_e = (const float*)d_in[5];
    const float* seq_p = (const float*)d_in[6];
    const int*   mask  = (const int*)d_in[7];
    const float* Wq    = (const float*)d_in[8];
    const float* Wk    = (const float*)d_in[9];
    const float* Wv    = (const float*)d_in[10];
    const float* w_map = (const float*)d_in[11];
    const float* fc_w  = (const float*)d_in[12];
    const float* fc_b  = (const float*)d_in[13];
    const float* ln_g  = (const float*)d_in[14];
    const float* ln_b  = (const float*)d_in[15];
    const float* fc1_w = (const float*)d_in[16];
    const float* fc1_b = (const float*)d_in[17];
    const float* fc2_w = (const float*)d_in[18];
    const float* fc2_b = (const float*)d_in[19];

    float* out      = (float*)d_out;
    float* z_out    = out;                 // [2048,1,128]
    float* attn_out = out + NB * DK;       // [2048,4,1,64]

    fold_kernel<<<DM, 128>>>(Wq, Wk, w_map);
    wtile_kernel<<<608, 256>>>(Wv, fc_w, fc1_w, fc2_w);

    score_kernel<<<NB, 256>>>(src, src_t, src_p, seq, seq_e, seq_t, seq_p,
                              mask, attn_out);

    const int smem2 = SM_TOTF * (int)sizeof(float);
    cudaFuncSetAttribute(tail_kernel, cudaFuncAttributeMaxDynamicSharedMemorySize, smem2);
    tail_kernel<<<NB / TB, 512, smem2>>>(src, src_t, src_p,
                                         seq, seq_e, seq_t, seq_p,
                                         fc_b, ln_g, ln_b, fc1_b, fc2_b, z_out);
}